// round 14
// baseline (speedup 1.0000x reference)
#include <cuda_runtime.h>
#include <cuda_fp16.h>
#include <cstdint>
#include <cstring>

#define B_ 256
#define N_ 256
#define F_ 64
#define H_ 512

// ---------------------------------------------------------------------------
// Scratch (static device globals — allocation-free per harness rules)
// ---------------------------------------------------------------------------
__device__ __align__(16) __half g_nA[(size_t)B_ * N_ * N_];
__device__ __align__(16) __half g_H[(size_t)B_ * N_ * H_];
__device__ __align__(16) __half g_Yt[(size_t)B_ * H_ * N_];
__device__ __align__(16) __half g_XW1t[H_ * N_];
__device__ __align__(16) __half g_w2t[H_ * H_];
__device__ __align__(16) __half g_w3t[H_ * H_];
__device__ float g_rowsum[B_ * N_];
__device__ float g_colpart[B_ * 8 * N_];
__device__ float g_dinv[B_ * N_];
__device__ float g_meanpart[2 * B_ * H_];

// ---------------------------------------------------------------------------
// Helpers (portable PTX only — no tcgen05 under this toolchain)
// ---------------------------------------------------------------------------
__device__ __forceinline__ uint32_t s2u(const void* p) {
    uint32_t a;
    asm("{ .reg .u64 t; cvta.to.shared.u64 t, %1; cvt.u32.u64 %0, t; }" : "=r"(a) : "l"(p));
    return a;
}
__device__ __forceinline__ void cpasync16(uint32_t dst, const void* src) {
    asm volatile("cp.async.cg.shared.global [%0], [%1], 16;" :: "r"(dst), "l"(src));
}
__device__ __forceinline__ void ldsm4(uint32_t addr, uint32_t* r) {
    asm volatile("ldmatrix.sync.aligned.m8n8.x4.shared.b16 {%0,%1,%2,%3}, [%4];"
                 : "=r"(r[0]), "=r"(r[1]), "=r"(r[2]), "=r"(r[3]) : "r"(addr));
}
__device__ __forceinline__ void mma16816(float* d, const uint32_t* a, const uint32_t* b) {
    asm volatile(
        "mma.sync.aligned.m16n8k16.row.col.f32.f16.f16.f32 "
        "{%0,%1,%2,%3}, {%4,%5,%6,%7}, {%8,%9}, {%0,%1,%2,%3};"
        : "+f"(d[0]), "+f"(d[1]), "+f"(d[2]), "+f"(d[3])
        : "r"(a[0]), "r"(a[1]), "r"(a[2]), "r"(a[3]), "r"(b[0]), "r"(b[1]));
}
__device__ __forceinline__ uint32_t pack2h(__half a, __half b) {
    unsigned short ua, ub;
    memcpy(&ua, &a, 2); memcpy(&ub, &b, 2);
    return (uint32_t)ua | ((uint32_t)ub << 16);
}
__device__ __forceinline__ float sigmoidf_(float x) { return 1.0f / (1.0f + expf(-x)); }
__device__ __forceinline__ float sigmoid_fast(float x) {
    float t;
    asm("tanh.approx.f32 %0, %1;" : "=f"(t) : "f"(0.5f * x));
    return fmaf(t, 0.5f, 0.5f);
}

// ---------------------------------------------------------------------------
// HMMA GEMM: 128(M) x 128(N) CTA tile, 128 threads (4 warps of 64x64),
// K via 64-wide chunks, 3-stage cp.async pipeline, single-pass fp16.
// 2 resident CTAs/SM (96KB smem). Single __syncthreads per chunk:
//   wait_group -> sync -> issue(c+2 into stage (c+2)%3) -> compute(c)
// The top sync proves all warps finished computing chunk c-1, so refilling
// stage (c-1)%3 == (c+2)%3 is safe without a bottom barrier.
// A row-major [M,KTOT]; B pre-transposed [N,KTOT].
// EPI: 0 = relu + row-major fp16 out; 1 = bias + transposed fp16 out;
//      2 = relu + column-sum partial reduce (mean path)
// ---------------------------------------------------------------------------
constexpr int APLANE = 16384;
constexpr int BPLANE = 16384;
constexpr int STAGE = APLANE + BPLANE;           // 32768
constexpr int SMEM_G = 3 * STAGE;                // 98304 per CTA (2 CTAs/SM)
constexpr int PADW = 129;                        // epilogue 128*129*4 = 66048 fits

__device__ __forceinline__ void issue_chunk(uint32_t sbase, int tid,
                                            const __half* ah, const __half* bh, int ldk) {
#pragma unroll
    for (int i = 0; i < 8; i++) {
        int idx = tid + i * 128;
        int row = idx >> 3, seg = idx & 7;
        size_t go = (size_t)row * ldk + seg * 8;
        uint32_t sw = (uint32_t)(row * 128) + (uint32_t)((seg ^ (row & 7)) << 4);
        cpasync16(sbase + sw, ah + go);
    }
#pragma unroll
    for (int i = 0; i < 8; i++) {
        int idx = tid + i * 128;
        int row = idx >> 3, seg = idx & 7;
        size_t go = (size_t)row * ldk + seg * 8;
        uint32_t sw = (uint32_t)(row * 128) + (uint32_t)((seg ^ (row & 7)) << 4);
        cpasync16(sbase + APLANE + sw, bh + go);
    }
    asm volatile("cp.async.commit_group;" ::: "memory");
}

template <int KTOT, int EPI>
__global__ void __launch_bounds__(128, 2) hgemm(
    const __half* __restrict__ A, long sA,
    const __half* __restrict__ Bh, long sB,
    const float* __restrict__ bias,
    __half* __restrict__ O,
    float* __restrict__ mp) {
    extern __shared__ __align__(1024) char smem[];
    uint32_t sb = s2u(smem);
    const int tid = threadIdx.x, lane = tid & 31, wid = tid >> 5;
    const int nT = blockIdx.x, mT = blockIdx.y, b = blockIdx.z;
    const int mBase = mT * 128, nBase = nT * 128;
    const int m0 = (wid & 1) * 64, n0w = (wid >> 1) * 64;

    const __half* pA = A + (size_t)b * sA + (size_t)mBase * KTOT;
    const __half* pB = Bh + (size_t)b * sB + (size_t)nBase * KTOT;

    constexpr int NCH = KTOT / 64;
    issue_chunk(sb + 0 * STAGE, tid, pA, pB, KTOT);
    issue_chunk(sb + 1 * STAGE, tid, pA + 64, pB + 64, KTOT);

    float acc[4][8][4] = {};

    const uint32_t aoff0 = (uint32_t)(m0 + (lane & 15)) * 128;
    const int ax = lane & 7, kb = lane >> 4;
    const int grp = lane >> 3;
    const int brow0 = n0w + (lane & 7) + ((grp & 2) << 2);
    const uint32_t boff0 = (uint32_t)brow0 * 128;
    const int bx = brow0 & 7, kgb = grp & 1;

    for (int c = 0; c < NCH; c++) {
        if (c + 1 < NCH) asm volatile("cp.async.wait_group 1;" ::: "memory");
        else             asm volatile("cp.async.wait_group 0;" ::: "memory");
        __syncthreads();
        if (c + 2 < NCH)
            issue_chunk(sb + ((c + 2) % 3) * STAGE, tid,
                        pA + (c + 2) * 64, pB + (c + 2) * 64, KTOT);

        const uint32_t s0 = sb + (c % 3) * STAGE;
#pragma unroll
        for (int ks = 0; ks < 4; ks++) {
            uint32_t ah[4][4], bf[4][4];
            const uint32_t kxa = (uint32_t)((((ks << 1) | kb)) ^ ax) << 4;
#pragma unroll
            for (int mt = 0; mt < 4; mt++)
                ldsm4(s0 + aoff0 + mt * 2048 + kxa, ah[mt]);
            const uint32_t kxb = (uint32_t)((((ks << 1) | kgb)) ^ bx) << 4;
#pragma unroll
            for (int np = 0; np < 4; np++)
                ldsm4(s0 + APLANE + boff0 + np * 2048 + kxb, bf[np]);
#pragma unroll
            for (int np = 0; np < 4; np++)
#pragma unroll
                for (int mt = 0; mt < 4; mt++)
#pragma unroll
                    for (int j = 0; j < 2; j++)
                        mma16816(acc[mt][np * 2 + j], ah[mt], bf[np] + 2 * j);
        }
    }
    __syncthreads();   // all warps done reading stage smem before staging reuse

    // accum -> padded fp32 smem (128 x 128, stride PADW)
    float* fsm = (float*)smem;
    {
        const int r0 = lane >> 2, c0 = (lane & 3) * 2;
#pragma unroll
        for (int mt = 0; mt < 4; mt++)
#pragma unroll
            for (int nt = 0; nt < 8; nt++) {
                int rr = m0 + mt * 16 + r0;
                int cc = n0w + nt * 8 + c0;
                fsm[rr * PADW + cc]           = acc[mt][nt][0];
                fsm[rr * PADW + cc + 1]       = acc[mt][nt][1];
                fsm[(rr + 8) * PADW + cc]     = acc[mt][nt][2];
                fsm[(rr + 8) * PADW + cc + 1] = acc[mt][nt][3];
            }
    }
    __syncthreads();

    if constexpr (EPI == 0) {
        // relu + fp16 row-major out; thread = 1 row of 128 cols
        const int row = tid;
        const float* src = fsm + row * PADW;
        size_t go = ((size_t)(b * N_ + mBase + row)) * H_ + nBase;
#pragma unroll
        for (int q = 0; q < 16; q++) {
            uint32_t hp[4];
#pragma unroll
            for (int j = 0; j < 4; j++) {
                float v0 = fmaxf(src[q * 8 + j * 2], 0.0f);
                float v1 = fmaxf(src[q * 8 + j * 2 + 1], 0.0f);
                hp[j] = pack2h(__float2half(v0), __float2half(v1));
            }
            *(uint4*)(O + go + q * 8) = make_uint4(hp[0], hp[1], hp[2], hp[3]);
        }
    } else if constexpr (EPI == 1) {
        // bias + fp16 transposed ([N,K]) out; thread = 1 n-row of 128 m
        const int n = tid;
        const float bv = bias[nBase + n];
        size_t go = ((size_t)(b * H_ + nBase + n)) * N_ + mBase;
#pragma unroll
        for (int q = 0; q < 16; q++) {
            uint32_t hp[4];
#pragma unroll
            for (int j = 0; j < 4; j++) {
                float v0 = fsm[(q * 8 + j * 2) * PADW + n] + bv;
                float v1 = fsm[(q * 8 + j * 2 + 1) * PADW + n] + bv;
                hp[j] = pack2h(__float2half(v0), __float2half(v1));
            }
            *(uint4*)(O + go + q * 8) = make_uint4(hp[0], hp[1], hp[2], hp[3]);
        }
    } else {
        // relu + partial column sums (mean path)
        const int col = tid;
        float s = 0.0f;
#pragma unroll 16
        for (int r = 0; r < 128; r++)
            s += fmaxf(fsm[r * PADW + col], 0.0f);
        mp[((size_t)mT * B_ + b) * H_ + nBase + col] = s;
    }
}

// ---------------------------------------------------------------------------
// Single-pass z reductions: ONE sigmoid per element. Row sums direct,
// column sums as per-strip partials (combined by dinv_kernel).
// grid (B_, 8 strips of 32 rows), block 256 (8 warps x 4 rows).
// ---------------------------------------------------------------------------
__global__ void zsums_kernel(const float* __restrict__ z) {
    int b = blockIdx.x, strip = blockIdx.y;
    int lane = threadIdx.x & 31, w = threadIdx.x >> 5;
    const float* Z = z + (size_t)b * N_ * N_ + (size_t)strip * 32 * N_;
    __shared__ float scol[8][N_];
    float colacc[8];
#pragma unroll
    for (int c = 0; c < 8; c++) colacc[c] = 0.0f;
#pragma unroll
    for (int rr = 0; rr < 4; rr++) {
        int row = w * 4 + rr;
        float rs = 0.0f;
#pragma unroll
        for (int c = 0; c < 8; c++) {
            float v = sigmoidf_(Z[(size_t)row * N_ + lane + 32 * c]);
            rs += v;
            colacc[c] += v;
        }
#pragma unroll
        for (int o = 16; o; o >>= 1) rs += __shfl_down_sync(0xffffffffu, rs, o);
        if (lane == 0) g_rowsum[b * N_ + strip * 32 + row] = rs;
    }
#pragma unroll
    for (int c = 0; c < 8; c++) scol[w][lane + 32 * c] = colacc[c];
    __syncthreads();
    int col = threadIdx.x;
    float s = scol[0][col];
#pragma unroll
    for (int k = 1; k < 8; k++) s += scol[k][col];
    g_colpart[((size_t)b * 8 + strip) * N_ + col] = s;
}

// Deterministic combine + dinv precompute. grid B_, 256 threads.
__global__ void dinv_kernel() {
    int b = blockIdx.x, col = threadIdx.x;
    const float* p = g_colpart + (size_t)b * 8 * N_;
    float s = p[col];
#pragma unroll
    for (int k = 1; k < 8; k++) s += p[k * N_ + col];
    float D = 1.0f + 0.5f * (g_rowsum[b * N_ + col] + s) + 1e-6f;
    g_dinv[b * N_ + col] = rsqrtf(D);
}

// ---------------------------------------------------------------------------
// Fused prep: blocks [0,128): XW1^T (2 nodes/block); [128,384): w2^T tile;
// [384,640): w3^T tile. 1024 threads. All outputs single fp16 (B-side).
// ---------------------------------------------------------------------------
__global__ void prep_kernel(const float* __restrict__ X, const float* __restrict__ w1,
                            const float* __restrict__ b1,
                            const float* __restrict__ w2, const float* __restrict__ w3) {
    int bx = blockIdx.x, tid = threadIdx.x;
    if (bx < 128) {
        int i = bx * 2 + (tid >> 9);   // node
        int h = tid & 511;
        __shared__ float xr[2][F_];
        if (h < F_) xr[tid >> 9][h] = X[i * F_ + h];
        __syncthreads();
        float acc = b1[h];
#pragma unroll 8
        for (int k = 0; k < F_; k++) acc = fmaf(xr[tid >> 9][k], w1[k * H_ + h], acc);
        g_XW1t[h * N_ + i] = __float2half(acc);
    } else {
        const float* w = (bx < 384) ? w2 : w3;
        __half* thi = (bx < 384) ? g_w2t : g_w3t;
        int t = (bx < 384) ? bx - 128 : bx - 384;
        int n0 = (t & 15) * 32, k0 = (t >> 4) * 32;
        int tx = tid & 31, ty = tid >> 5;
        __shared__ float tt[32][33];
        tt[ty][tx] = w[(k0 + ty) * H_ + n0 + tx];
        __syncthreads();
        thi[(n0 + ty) * H_ + k0 + tx] = __float2half(tt[tx][ty]);
    }
}

// ---------------------------------------------------------------------------
// normA symmetric tile-pair kernel, vectorized: 256 threads, 4 elems/thread,
// float4 z loads, smem-cached dinv, uint2 (4 x fp16) stores. z read once.
// grid (36 upper-tri block pairs, B_).
// ---------------------------------------------------------------------------
__global__ void __launch_bounds__(256) norma_kernel(const float* __restrict__ z) {
    int p = blockIdx.x, b = blockIdx.y;
    int bi = 0, rem = p;
    while (rem >= 8 - bi) { rem -= 8 - bi; bi++; }
    int bj = bi + rem;
    int i0 = bi * 32, j0 = bj * 32;
    const int tid = threadIdx.x;
    const int ty = tid >> 3;
    const int tx4 = (tid & 7) * 4;

    __shared__ float tA[32][33];
    __shared__ float tB[32][33];
    __shared__ float di[32], dj[32];

    const float* Z = z + (size_t)b * N_ * N_;
    const bool diag = (bi == bj);

    float4 va = *(const float4*)&Z[(size_t)(i0 + ty) * N_ + j0 + tx4];
    tA[ty][tx4 + 0] = sigmoid_fast(va.x);
    tA[ty][tx4 + 1] = sigmoid_fast(va.y);
    tA[ty][tx4 + 2] = sigmoid_fast(va.z);
    tA[ty][tx4 + 3] = sigmoid_fast(va.w);
    if (!diag) {
        float4 vb = *(const float4*)&Z[(size_t)(j0 + ty) * N_ + i0 + tx4];
        tB[ty][tx4 + 0] = sigmoid_fast(vb.x);
        tB[ty][tx4 + 1] = sigmoid_fast(vb.y);
        tB[ty][tx4 + 2] = sigmoid_fast(vb.z);
        tB[ty][tx4 + 3] = sigmoid_fast(vb.w);
    }
    if (tid < 32)              di[tid] = g_dinv[b * N_ + i0 + tid];
    else if (tid < 64)         dj[tid - 32] = g_dinv[b * N_ + j0 + tid - 32];
    __syncthreads();

    {
        const float dv = di[ty];
        __half h[4];
#pragma unroll
        for (int k = 0; k < 4; k++) {
            int j = tx4 + k;
            float at = diag ? tA[j][ty] : tB[j][ty];
            float v = 0.5f * (tA[ty][j] + at);
            if (diag && ty == j) v += 1.0f;
            h[k] = __float2half(v * dv * dj[j]);
        }
        uint2 pk = make_uint2(pack2h(h[0], h[1]), pack2h(h[2], h[3]));
        *(uint2*)&g_nA[(size_t)b * N_ * N_ + (size_t)(i0 + ty) * N_ + j0 + tx4] = pk;
    }
    if (!diag) {
        const float dv = dj[ty];
        __half h[4];
#pragma unroll
        for (int k = 0; k < 4; k++) {
            int j = tx4 + k;
            float v = 0.5f * (tB[ty][j] + tA[j][ty]);
            h[k] = __float2half(v * dv * di[j]);
        }
        uint2 pk = make_uint2(pack2h(h[0], h[1]), pack2h(h[2], h[3]));
        *(uint2*)&g_nA[(size_t)b * N_ * N_ + (size_t)(j0 + ty) * N_ + i0 + tx4] = pk;
    }
}

// ---------------------------------------------------------------------------
// logits from meanpart
// ---------------------------------------------------------------------------
__global__ void readout_kernel(const float* __restrict__ fcw, const float* __restrict__ fcb,
                               float* __restrict__ out) {
    int b = blockIdx.x;
    int h = threadIdx.x;
    float ge = (g_meanpart[b * H_ + h] + g_meanpart[B_ * H_ + b * H_ + h]) * (1.0f / N_);
    __shared__ float s0[H_], s1[H_];
    s0[h] = ge * fcw[h * 2 + 0];
    s1[h] = ge * fcw[h * 2 + 1];
    __syncthreads();
    for (int st = 256; st > 0; st >>= 1) {
        if (h < st) { s0[h] += s0[h + st]; s1[h] += s1[h + st]; }
        __syncthreads();
    }
    if (h == 0) {
        out[b * 2 + 0] = s0[0] + fcb[0];
        out[b * 2 + 1] = s1[0] + fcb[1];
    }
}

// ---------------------------------------------------------------------------
extern "C" void kernel_launch(void* const* d_in, const int* in_sizes, int n_in,
                              void* d_out, int out_size) {
    const float* z   = (const float*)d_in[0];
    const float* ne  = (const float*)d_in[1];
    const float* w1  = (const float*)d_in[2];
    const float* b1  = (const float*)d_in[3];
    const float* w2  = (const float*)d_in[4];
    const float* b2  = (const float*)d_in[5];
    const float* w3  = (const float*)d_in[6];
    const float* b3  = (const float*)d_in[7];
    const float* fcw = (const float*)d_in[8];
    const float* fcb = (const float*)d_in[9];
    float* out = (float*)d_out;

    __half *pnA, *pH, *pYt, *pXW1t, *pw2t, *pw3t;
    float* pmean;
    cudaGetSymbolAddress((void**)&pnA, g_nA);
    cudaGetSymbolAddress((void**)&pH, g_H);
    cudaGetSymbolAddress((void**)&pYt, g_Yt);
    cudaGetSymbolAddress((void**)&pXW1t, g_XW1t);
    cudaGetSymbolAddress((void**)&pw2t, g_w2t);
    cudaGetSymbolAddress((void**)&pw3t, g_w3t);
    cudaGetSymbolAddress((void**)&pmean, g_meanpart);

    cudaFuncSetAttribute(hgemm<256, 0>, cudaFuncAttributeMaxDynamicSharedMemorySize, SMEM_G);
    cudaFuncSetAttribute(hgemm<512, 1>, cudaFuncAttributeMaxDynamicSharedMemorySize, SMEM_G);
    cudaFuncSetAttribute(hgemm<256, 2>, cudaFuncAttributeMaxDynamicSharedMemorySize, SMEM_G);

    zsums_kernel<<<dim3(B_, 8), 256>>>(z);
    dinv_kernel<<<B_, 256>>>();
    prep_kernel<<<640, 1024>>>(ne, w1, b1, w2, w3);
    norma_kernel<<<dim3(36, B_), 256>>>(z);

    dim3 gg(4, 2, B_);   // nT (128-wide), mT (128-tall), batch
    // H1 = relu(normA @ XW1)
    hgemm<256, 0><<<gg, 128, SMEM_G>>>(pnA, (long)N_ * N_, pXW1t, 0, nullptr, pH, nullptr);
    // Y2^T = (H1 @ w2 + b2)^T
    hgemm<512, 1><<<gg, 128, SMEM_G>>>(pH, (long)N_ * H_, pw2t, 0, b2, pYt, nullptr);
    // H2 = relu(normA @ Y2)
    hgemm<256, 0><<<gg, 128, SMEM_G>>>(pnA, (long)N_ * N_, pYt, (long)H_ * N_, nullptr, pH, nullptr);
    // Y3^T = (H2 @ w3 + b3)^T
    hgemm<512, 1><<<gg, 128, SMEM_G>>>(pH, (long)N_ * H_, pw3t, 0, b3, pYt, nullptr);
    // meanpart = colsum(relu(normA @ Y3)) per m-tile
    hgemm<256, 2><<<gg, 128, SMEM_G>>>(pnA, (long)N_ * N_, pYt, (long)H_ * N_, nullptr, nullptr, pmean);

    readout_kernel<<<B_, H_>>>(fcw, fcb, out);
}

// round 15
// speedup vs baseline: 1.0665x; 1.0665x over previous
#include <cuda_runtime.h>
#include <cuda_fp16.h>
#include <cstdint>
#include <cstring>

#define B_ 256
#define N_ 256
#define F_ 64
#define H_ 512

// ---------------------------------------------------------------------------
// Scratch (static device globals — allocation-free per harness rules)
// ---------------------------------------------------------------------------
__device__ __align__(16) __half g_nA[(size_t)B_ * N_ * N_];
__device__ __align__(16) __half g_H[(size_t)B_ * N_ * H_];
__device__ __align__(16) __half g_Yt[(size_t)B_ * H_ * N_];
__device__ __align__(16) __half g_XW1t[H_ * N_];
__device__ __align__(16) __half g_w2t[H_ * H_];
__device__ __align__(16) __half g_w3t[H_ * H_];
__device__ float g_rowsum[B_ * N_];
__device__ float g_colpart[B_ * 8 * N_];
__device__ float g_dinv[B_ * N_];
__device__ float g_meanpart[2 * B_ * H_];

// ---------------------------------------------------------------------------
// Helpers (portable PTX only — no tcgen05 under this toolchain)
// ---------------------------------------------------------------------------
__device__ __forceinline__ uint32_t s2u(const void* p) {
    uint32_t a;
    asm("{ .reg .u64 t; cvta.to.shared.u64 t, %1; cvt.u32.u64 %0, t; }" : "=r"(a) : "l"(p));
    return a;
}
__device__ __forceinline__ void cpasync16(uint32_t dst, const void* src) {
    asm volatile("cp.async.cg.shared.global [%0], [%1], 16;" :: "r"(dst), "l"(src));
}
__device__ __forceinline__ void ldsm4(uint32_t addr, uint32_t* r) {
    asm volatile("ldmatrix.sync.aligned.m8n8.x4.shared.b16 {%0,%1,%2,%3}, [%4];"
                 : "=r"(r[0]), "=r"(r[1]), "=r"(r[2]), "=r"(r[3]) : "r"(addr));
}
__device__ __forceinline__ void mma16816(float* d, const uint32_t* a, const uint32_t* b) {
    asm volatile(
        "mma.sync.aligned.m16n8k16.row.col.f32.f16.f16.f32 "
        "{%0,%1,%2,%3}, {%4,%5,%6,%7}, {%8,%9}, {%0,%1,%2,%3};"
        : "+f"(d[0]), "+f"(d[1]), "+f"(d[2]), "+f"(d[3])
        : "r"(a[0]), "r"(a[1]), "r"(a[2]), "r"(a[3]), "r"(b[0]), "r"(b[1]));
}
__device__ __forceinline__ uint32_t pack2h(__half a, __half b) {
    unsigned short ua, ub;
    memcpy(&ua, &a, 2); memcpy(&ub, &b, 2);
    return (uint32_t)ua | ((uint32_t)ub << 16);
}
// MUFU-based sigmoid (ex2 + fast rcp): rel err ~1e-6 — safe for degree sums
__device__ __forceinline__ float sigmoid_mufu(float x) {
    return __fdividef(1.0f, 1.0f + __expf(-x));
}
// tanh.approx sigmoid (1 MUFU op, ~3e-4 abs err) — per-element in norma only
__device__ __forceinline__ float sigmoid_fast(float x) {
    float t;
    asm("tanh.approx.f32 %0, %1;" : "=f"(t) : "f"(0.5f * x));
    return fmaf(t, 0.5f, 0.5f);
}

// ---------------------------------------------------------------------------
// HMMA GEMM: 128(M) x 128(N) CTA tile, 128 threads (4 warps of 64x64),
// K via 64-wide chunks, 3-stage cp.async pipeline, single-pass fp16.
// 2 resident CTAs/SM (96KB smem) decorrelate barrier/prologue/epilogue bubbles.
// A row-major [M,KTOT]; B pre-transposed [N,KTOT].
// EPI: 0 = relu + row-major fp16 out; 1 = bias + transposed fp16 out;
//      2 = relu + column-sum partial reduce (mean path)
// ---------------------------------------------------------------------------
constexpr int APLANE = 16384;
constexpr int BPLANE = 16384;
constexpr int STAGE = APLANE + BPLANE;           // 32768
constexpr int SMEM_G = 3 * STAGE;                // 98304 per CTA (2 CTAs/SM)
constexpr int PADW = 129;                        // epilogue 128*129*4 = 66048 fits

__device__ __forceinline__ void issue_chunk(uint32_t sbase, int tid,
                                            const __half* ah, const __half* bh, int ldk) {
#pragma unroll
    for (int i = 0; i < 8; i++) {
        int idx = tid + i * 128;
        int row = idx >> 3, seg = idx & 7;
        size_t go = (size_t)row * ldk + seg * 8;
        uint32_t sw = (uint32_t)(row * 128) + (uint32_t)((seg ^ (row & 7)) << 4);
        cpasync16(sbase + sw, ah + go);
    }
#pragma unroll
    for (int i = 0; i < 8; i++) {
        int idx = tid + i * 128;
        int row = idx >> 3, seg = idx & 7;
        size_t go = (size_t)row * ldk + seg * 8;
        uint32_t sw = (uint32_t)(row * 128) + (uint32_t)((seg ^ (row & 7)) << 4);
        cpasync16(sbase + APLANE + sw, bh + go);
    }
    asm volatile("cp.async.commit_group;" ::: "memory");
}

template <int KTOT, int EPI>
__global__ void __launch_bounds__(128, 2) hgemm(
    const __half* __restrict__ A, long sA,
    const __half* __restrict__ Bh, long sB,
    const float* __restrict__ bias,
    __half* __restrict__ O,
    float* __restrict__ mp) {
    extern __shared__ __align__(1024) char smem[];
    uint32_t sb = s2u(smem);
    const int tid = threadIdx.x, lane = tid & 31, wid = tid >> 5;
    const int nT = blockIdx.x, mT = blockIdx.y, b = blockIdx.z;
    const int mBase = mT * 128, nBase = nT * 128;
    const int m0 = (wid & 1) * 64, n0w = (wid >> 1) * 64;

    const __half* pA = A + (size_t)b * sA + (size_t)mBase * KTOT;
    const __half* pB = Bh + (size_t)b * sB + (size_t)nBase * KTOT;

    constexpr int NCH = KTOT / 64;
    issue_chunk(sb + 0 * STAGE, tid, pA, pB, KTOT);
    issue_chunk(sb + 1 * STAGE, tid, pA + 64, pB + 64, KTOT);
    issue_chunk(sb + 2 * STAGE, tid, pA + 128, pB + 128, KTOT);

    float acc[4][8][4] = {};

    const uint32_t aoff0 = (uint32_t)(m0 + (lane & 15)) * 128;
    const int ax = lane & 7, kb = lane >> 4;
    const int grp = lane >> 3;
    const int brow0 = n0w + (lane & 7) + ((grp & 2) << 2);
    const uint32_t boff0 = (uint32_t)brow0 * 128;
    const int bx = brow0 & 7, kgb = grp & 1;

    for (int c = 0; c < NCH; c++) {
        if (NCH - 1 - c >= 2)      asm volatile("cp.async.wait_group 2;" ::: "memory");
        else if (NCH - 1 - c == 1) asm volatile("cp.async.wait_group 1;" ::: "memory");
        else                       asm volatile("cp.async.wait_group 0;" ::: "memory");
        __syncthreads();

        const uint32_t s0 = sb + (c % 3) * STAGE;
#pragma unroll
        for (int ks = 0; ks < 4; ks++) {
            uint32_t ah[4][4], bf[4][4];
            const uint32_t kxa = (uint32_t)((((ks << 1) | kb)) ^ ax) << 4;
#pragma unroll
            for (int mt = 0; mt < 4; mt++)
                ldsm4(s0 + aoff0 + mt * 2048 + kxa, ah[mt]);
            const uint32_t kxb = (uint32_t)((((ks << 1) | kgb)) ^ bx) << 4;
#pragma unroll
            for (int np = 0; np < 4; np++)
                ldsm4(s0 + APLANE + boff0 + np * 2048 + kxb, bf[np]);
#pragma unroll
            for (int np = 0; np < 4; np++)
#pragma unroll
                for (int mt = 0; mt < 4; mt++)
#pragma unroll
                    for (int j = 0; j < 2; j++)
                        mma16816(acc[mt][np * 2 + j], ah[mt], bf[np] + 2 * j);
        }
        __syncthreads();
        if (c + 3 < NCH)
            issue_chunk(sb + (c % 3) * STAGE, tid,
                        pA + (c + 3) * 64, pB + (c + 3) * 64, KTOT);
    }

    // accum -> padded fp32 smem (128 x 128, stride PADW)
    float* fsm = (float*)smem;
    {
        const int r0 = lane >> 2, c0 = (lane & 3) * 2;
#pragma unroll
        for (int mt = 0; mt < 4; mt++)
#pragma unroll
            for (int nt = 0; nt < 8; nt++) {
                int rr = m0 + mt * 16 + r0;
                int cc = n0w + nt * 8 + c0;
                fsm[rr * PADW + cc]           = acc[mt][nt][0];
                fsm[rr * PADW + cc + 1]       = acc[mt][nt][1];
                fsm[(rr + 8) * PADW + cc]     = acc[mt][nt][2];
                fsm[(rr + 8) * PADW + cc + 1] = acc[mt][nt][3];
            }
    }
    __syncthreads();

    if constexpr (EPI == 0) {
        // relu + fp16 row-major out; thread = 1 row of 128 cols
        const int row = tid;
        const float* src = fsm + row * PADW;
        size_t go = ((size_t)(b * N_ + mBase + row)) * H_ + nBase;
#pragma unroll
        for (int q = 0; q < 16; q++) {
            uint32_t hp[4];
#pragma unroll
            for (int j = 0; j < 4; j++) {
                float v0 = fmaxf(src[q * 8 + j * 2], 0.0f);
                float v1 = fmaxf(src[q * 8 + j * 2 + 1], 0.0f);
                hp[j] = pack2h(__float2half(v0), __float2half(v1));
            }
            *(uint4*)(O + go + q * 8) = make_uint4(hp[0], hp[1], hp[2], hp[3]);
        }
    } else if constexpr (EPI == 1) {
        // bias + fp16 transposed ([N,K]) out; thread = 1 n-row of 128 m
        const int n = tid;
        const float bv = bias[nBase + n];
        size_t go = ((size_t)(b * H_ + nBase + n)) * N_ + mBase;
#pragma unroll
        for (int q = 0; q < 16; q++) {
            uint32_t hp[4];
#pragma unroll
            for (int j = 0; j < 4; j++) {
                float v0 = fsm[(q * 8 + j * 2) * PADW + n] + bv;
                float v1 = fsm[(q * 8 + j * 2 + 1) * PADW + n] + bv;
                hp[j] = pack2h(__float2half(v0), __float2half(v1));
            }
            *(uint4*)(O + go + q * 8) = make_uint4(hp[0], hp[1], hp[2], hp[3]);
        }
    } else {
        // relu + partial column sums (mean path)
        const int col = tid;
        float s = 0.0f;
#pragma unroll 16
        for (int r = 0; r < 128; r++)
            s += fmaxf(fsm[r * PADW + col], 0.0f);
        mp[((size_t)mT * B_ + b) * H_ + nBase + col] = s;
    }
}

// ---------------------------------------------------------------------------
// Single-pass z reductions with MUFU sigmoid: ONE sigmoid per element.
// Row sums direct; column sums as per-strip partials (combined by dinv_kernel).
// grid (B_, 8 strips of 32 rows), block 256 (8 warps x 4 rows).
// ---------------------------------------------------------------------------
__global__ void zsums_kernel(const float* __restrict__ z) {
    int b = blockIdx.x, strip = blockIdx.y;
    int lane = threadIdx.x & 31, w = threadIdx.x >> 5;
    const float* Z = z + (size_t)b * N_ * N_ + (size_t)strip * 32 * N_;
    __shared__ float scol[8][N_];
    float colacc[8];
#pragma unroll
    for (int c = 0; c < 8; c++) colacc[c] = 0.0f;
#pragma unroll
    for (int rr = 0; rr < 4; rr++) {
        int row = w * 4 + rr;
        float rs = 0.0f;
#pragma unroll
        for (int c = 0; c < 8; c++) {
            float v = sigmoid_mufu(Z[(size_t)row * N_ + lane + 32 * c]);
            rs += v;
            colacc[c] += v;
        }
#pragma unroll
        for (int o = 16; o; o >>= 1) rs += __shfl_down_sync(0xffffffffu, rs, o);
        if (lane == 0) g_rowsum[b * N_ + strip * 32 + row] = rs;
    }
#pragma unroll
    for (int c = 0; c < 8; c++) scol[w][lane + 32 * c] = colacc[c];
    __syncthreads();
    int col = threadIdx.x;
    float s = scol[0][col];
#pragma unroll
    for (int k = 1; k < 8; k++) s += scol[k][col];
    g_colpart[((size_t)b * 8 + strip) * N_ + col] = s;
}

// Deterministic combine + dinv precompute. grid B_, 256 threads.
__global__ void dinv_kernel() {
    int b = blockIdx.x, col = threadIdx.x;
    const float* p = g_colpart + (size_t)b * 8 * N_;
    float s = p[col];
#pragma unroll
    for (int k = 1; k < 8; k++) s += p[k * N_ + col];
    float D = 1.0f + 0.5f * (g_rowsum[b * N_ + col] + s) + 1e-6f;
    g_dinv[b * N_ + col] = rsqrtf(D);
}

// ---------------------------------------------------------------------------
// Fused prep: blocks [0,128): XW1^T (2 nodes/block); [128,384): w2^T tile;
// [384,640): w3^T tile. 1024 threads. All outputs single fp16 (B-side).
// ---------------------------------------------------------------------------
__global__ void prep_kernel(const float* __restrict__ X, const float* __restrict__ w1,
                            const float* __restrict__ b1,
                            const float* __restrict__ w2, const float* __restrict__ w3) {
    int bx = blockIdx.x, tid = threadIdx.x;
    if (bx < 128) {
        int i = bx * 2 + (tid >> 9);   // node
        int h = tid & 511;
        __shared__ float xr[2][F_];
        if (h < F_) xr[tid >> 9][h] = X[i * F_ + h];
        __syncthreads();
        float acc = b1[h];
#pragma unroll 8
        for (int k = 0; k < F_; k++) acc = fmaf(xr[tid >> 9][k], w1[k * H_ + h], acc);
        g_XW1t[h * N_ + i] = __float2half(acc);
    } else {
        const float* w = (bx < 384) ? w2 : w3;
        __half* thi = (bx < 384) ? g_w2t : g_w3t;
        int t = (bx < 384) ? bx - 128 : bx - 384;
        int n0 = (t & 15) * 32, k0 = (t >> 4) * 32;
        int tx = tid & 31, ty = tid >> 5;
        __shared__ float tt[32][33];
        tt[ty][tx] = w[(k0 + ty) * H_ + n0 + tx];
        __syncthreads();
        thi[(n0 + ty) * H_ + k0 + tx] = __float2half(tt[tx][ty]);
    }
}

// ---------------------------------------------------------------------------
// normA symmetric tile-pair kernel, vectorized: 256 threads, 4 elems/thread,
// float4 z loads, smem-cached dinv, uint2 (4 x fp16) stores. z read once.
// grid (36 upper-tri block pairs, B_).
// ---------------------------------------------------------------------------
__global__ void __launch_bounds__(256) norma_kernel(const float* __restrict__ z) {
    int p = blockIdx.x, b = blockIdx.y;
    int bi = 0, rem = p;
    while (rem >= 8 - bi) { rem -= 8 - bi; bi++; }
    int bj = bi + rem;
    int i0 = bi * 32, j0 = bj * 32;
    const int tid = threadIdx.x;
    const int ty = tid >> 3;
    const int tx4 = (tid & 7) * 4;

    __shared__ float tA[32][33];
    __shared__ float tB[32][33];
    __shared__ float di[32], dj[32];

    const float* Z = z + (size_t)b * N_ * N_;
    const bool diag = (bi == bj);

    float4 va = *(const float4*)&Z[(size_t)(i0 + ty) * N_ + j0 + tx4];
    tA[ty][tx4 + 0] = sigmoid_fast(va.x);
    tA[ty][tx4 + 1] = sigmoid_fast(va.y);
    tA[ty][tx4 + 2] = sigmoid_fast(va.z);
    tA[ty][tx4 + 3] = sigmoid_fast(va.w);
    if (!diag) {
        float4 vb = *(const float4*)&Z[(size_t)(j0 + ty) * N_ + i0 + tx4];
        tB[ty][tx4 + 0] = sigmoid_fast(vb.x);
        tB[ty][tx4 + 1] = sigmoid_fast(vb.y);
        tB[ty][tx4 + 2] = sigmoid_fast(vb.z);
        tB[ty][tx4 + 3] = sigmoid_fast(vb.w);
    }
    if (tid < 32)              di[tid] = g_dinv[b * N_ + i0 + tid];
    else if (tid < 64)         dj[tid - 32] = g_dinv[b * N_ + j0 + tid - 32];
    __syncthreads();

    {
        const float dv = di[ty];
        __half h[4];
#pragma unroll
        for (int k = 0; k < 4; k++) {
            int j = tx4 + k;
            float at = diag ? tA[j][ty] : tB[j][ty];
            float v = 0.5f * (tA[ty][j] + at);
            if (diag && ty == j) v += 1.0f;
            h[k] = __float2half(v * dv * dj[j]);
        }
        uint2 pk = make_uint2(pack2h(h[0], h[1]), pack2h(h[2], h[3]));
        *(uint2*)&g_nA[(size_t)b * N_ * N_ + (size_t)(i0 + ty) * N_ + j0 + tx4] = pk;
    }
    if (!diag) {
        const float dv = dj[ty];
        __half h[4];
#pragma unroll
        for (int k = 0; k < 4; k++) {
            int j = tx4 + k;
            float v = 0.5f * (tB[ty][j] + tA[j][ty]);
            h[k] = __float2half(v * dv * di[j]);
        }
        uint2 pk = make_uint2(pack2h(h[0], h[1]), pack2h(h[2], h[3]));
        *(uint2*)&g_nA[(size_t)b * N_ * N_ + (size_t)(j0 + ty) * N_ + i0 + tx4] = pk;
    }
}

// ---------------------------------------------------------------------------
// logits from meanpart
// ---------------------------------------------------------------------------
__global__ void readout_kernel(const float* __restrict__ fcw, const float* __restrict__ fcb,
                               float* __restrict__ out) {
    int b = blockIdx.x;
    int h = threadIdx.x;
    float ge = (g_meanpart[b * H_ + h] + g_meanpart[B_ * H_ + b * H_ + h]) * (1.0f / N_);
    __shared__ float s0[H_], s1[H_];
    s0[h] = ge * fcw[h * 2 + 0];
    s1[h] = ge * fcw[h * 2 + 1];
    __syncthreads();
    for (int st = 256; st > 0; st >>= 1) {
        if (h < st) { s0[h] += s0[h + st]; s1[h] += s1[h + st]; }
        __syncthreads();
    }
    if (h == 0) {
        out[b * 2 + 0] = s0[0] + fcb[0];
        out[b * 2 + 1] = s1[0] + fcb[1];
    }
}

// ---------------------------------------------------------------------------
extern "C" void kernel_launch(void* const* d_in, const int* in_sizes, int n_in,
                              void* d_out, int out_size) {
    const float* z   = (const float*)d_in[0];
    const float* ne  = (const float*)d_in[1];
    const float* w1  = (const float*)d_in[2];
    const float* b1  = (const float*)d_in[3];
    const float* w2  = (const float*)d_in[4];
    const float* b2  = (const float*)d_in[5];
    const float* w3  = (const float*)d_in[6];
    const float* b3  = (const float*)d_in[7];
    const float* fcw = (const float*)d_in[8];
    const float* fcb = (const float*)d_in[9];
    float* out = (float*)d_out;

    __half *pnA, *pH, *pYt, *pXW1t, *pw2t, *pw3t;
    float* pmean;
    cudaGetSymbolAddress((void**)&pnA, g_nA);
    cudaGetSymbolAddress((void**)&pH, g_H);
    cudaGetSymbolAddress((void**)&pYt, g_Yt);
    cudaGetSymbolAddress((void**)&pXW1t, g_XW1t);
    cudaGetSymbolAddress((void**)&pw2t, g_w2t);
    cudaGetSymbolAddress((void**)&pw3t, g_w3t);
    cudaGetSymbolAddress((void**)&pmean, g_meanpart);

    cudaFuncSetAttribute(hgemm<256, 0>, cudaFuncAttributeMaxDynamicSharedMemorySize, SMEM_G);
    cudaFuncSetAttribute(hgemm<512, 1>, cudaFuncAttributeMaxDynamicSharedMemorySize, SMEM_G);
    cudaFuncSetAttribute(hgemm<256, 2>, cudaFuncAttributeMaxDynamicSharedMemorySize, SMEM_G);

    zsums_kernel<<<dim3(B_, 8), 256>>>(z);
    dinv_kernel<<<B_, 256>>>();
    prep_kernel<<<640, 1024>>>(ne, w1, b1, w2, w3);
    norma_kernel<<<dim3(36, B_), 256>>>(z);

    dim3 gg(4, 2, B_);   // nT (128-wide), mT (128-tall), batch
    // H1 = relu(normA @ XW1)
    hgemm<256, 0><<<gg, 128, SMEM_G>>>(pnA, (long)N_ * N_, pXW1t, 0, nullptr, pH, nullptr);
    // Y2^T = (H1 @ w2 + b2)^T
    hgemm<512, 1><<<gg, 128, SMEM_G>>>(pH, (long)N_ * H_, pw2t, 0, b2, pYt, nullptr);
    // H2 = relu(normA @ Y2)
    hgemm<256, 0><<<gg, 128, SMEM_G>>>(pnA, (long)N_ * N_, pYt, (long)H_ * N_, nullptr, pH, nullptr);
    // Y3^T = (H2 @ w3 + b3)^T
    hgemm<512, 1><<<gg, 128, SMEM_G>>>(pH, (long)N_ * H_, pw3t, 0, b3, pYt, nullptr);
    // meanpart = colsum(relu(normA @ Y3)) per m-tile
    hgemm<256, 2><<<gg, 128, SMEM_G>>>(pnA, (long)N_ * N_, pYt, (long)H_ * N_, nullptr, nullptr, pmean);

    readout_kernel<<<B_, H_>>>(fcw, fcb, out);
}

// round 16
// speedup vs baseline: 1.0866x; 1.0189x over previous
#include <cuda_runtime.h>
#include <cuda_fp16.h>
#include <cstdint>
#include <cstring>

#define B_ 256
#define N_ 256
#define F_ 64
#define H_ 512

// ---------------------------------------------------------------------------
// Scratch (static device globals — allocation-free per harness rules)
// ---------------------------------------------------------------------------
__device__ __align__(16) __half g_nA[(size_t)B_ * N_ * N_];
__device__ __align__(16) __half g_H[(size_t)B_ * N_ * H_];
__device__ __align__(16) __half g_Yt[(size_t)B_ * H_ * N_];
__device__ __align__(16) __half g_XW1t[H_ * N_];
__device__ __align__(16) __half g_w2t[H_ * H_];
__device__ __align__(16) __half g_w3t[H_ * H_];
__device__ float g_rowsum[B_ * N_];
__device__ float g_colpart[B_ * 8 * N_];
__device__ float g_dinv[B_ * N_];
__device__ float g_meanpart[4 * B_ * H_];   // 4 mT partials

// ---------------------------------------------------------------------------
// Helpers (portable PTX only — no tcgen05 under this toolchain)
// ---------------------------------------------------------------------------
__device__ __forceinline__ uint32_t s2u(const void* p) {
    uint32_t a;
    asm("{ .reg .u64 t; cvta.to.shared.u64 t, %1; cvt.u32.u64 %0, t; }" : "=r"(a) : "l"(p));
    return a;
}
__device__ __forceinline__ void cpasync16(uint32_t dst, const void* src) {
    asm volatile("cp.async.cg.shared.global [%0], [%1], 16;" :: "r"(dst), "l"(src));
}
__device__ __forceinline__ void ldsm4(uint32_t addr, uint32_t* r) {
    asm volatile("ldmatrix.sync.aligned.m8n8.x4.shared.b16 {%0,%1,%2,%3}, [%4];"
                 : "=r"(r[0]), "=r"(r[1]), "=r"(r[2]), "=r"(r[3]) : "r"(addr));
}
__device__ __forceinline__ void mma16816(float* d, const uint32_t* a, const uint32_t* b) {
    asm volatile(
        "mma.sync.aligned.m16n8k16.row.col.f32.f16.f16.f32 "
        "{%0,%1,%2,%3}, {%4,%5,%6,%7}, {%8,%9}, {%0,%1,%2,%3};"
        : "+f"(d[0]), "+f"(d[1]), "+f"(d[2]), "+f"(d[3])
        : "r"(a[0]), "r"(a[1]), "r"(a[2]), "r"(a[3]), "r"(b[0]), "r"(b[1]));
}
__device__ __forceinline__ uint32_t pack2h(__half a, __half b) {
    unsigned short ua, ub;
    memcpy(&ua, &a, 2); memcpy(&ub, &b, 2);
    return (uint32_t)ua | ((uint32_t)ub << 16);
}
// MUFU-based sigmoid (ex2 + fast rcp): rel err ~1e-6 — safe for degree sums
__device__ __forceinline__ float sigmoid_mufu(float x) {
    return __fdividef(1.0f, 1.0f + __expf(-x));
}
// tanh.approx sigmoid (1 MUFU op) — per-element in norma only
__device__ __forceinline__ float sigmoid_fast(float x) {
    float t;
    asm("tanh.approx.f32 %0, %1;" : "=f"(t) : "f"(0.5f * x));
    return fmaf(t, 0.5f, 0.5f);
}

// ---------------------------------------------------------------------------
// HMMA GEMM: 64(M) x 128(N) CTA tile, 64 threads (2 warps of 64x64),
// K via 64-wide chunks, 2-stage cp.async pipeline, single-pass fp16.
// 48KB smem/CTA -> 4 resident CTAs/SM: maximal independent-CTA decorrelation
// of barrier/prologue/epilogue bubbles with the 64x64 warp tile intact
// (unchanged LDS-per-MMA ratio — the R13 failure mode avoided).
// A row-major [M,KTOT]; B pre-transposed [N,KTOT].
// EPI: 0 = relu + row-major fp16 out; 1 = bias + transposed fp16 out;
//      2 = relu + column-sum partial reduce (mean path)
// ---------------------------------------------------------------------------
constexpr int APLANE = 8192;                     // 64 rows x 128B
constexpr int BPLANE = 16384;                    // 128 rows x 128B
constexpr int STAGE = APLANE + BPLANE;           // 24576
constexpr int SMEM_G = 2 * STAGE;                // 49152 per CTA (4 CTAs/SM)
constexpr int PADW = 129;                        // epilogue 64*129*4 = 33024 fits

__device__ __forceinline__ void issue_chunk(uint32_t sbase, int tid,
                                            const __half* ah, const __half* bh, int ldk) {
    // A plane: 64 rows x 8 segs = 512 chunks of 16B; 8 per thread
#pragma unroll
    for (int i = 0; i < 8; i++) {
        int idx = tid + i * 64;
        int row = idx >> 3, seg = idx & 7;
        size_t go = (size_t)row * ldk + seg * 8;
        uint32_t sw = (uint32_t)(row * 128) + (uint32_t)((seg ^ (row & 7)) << 4);
        cpasync16(sbase + sw, ah + go);
    }
    // B plane: 128 rows x 8 segs = 1024 chunks; 16 per thread
#pragma unroll
    for (int i = 0; i < 16; i++) {
        int idx = tid + i * 64;
        int row = idx >> 3, seg = idx & 7;
        size_t go = (size_t)row * ldk + seg * 8;
        uint32_t sw = (uint32_t)(row * 128) + (uint32_t)((seg ^ (row & 7)) << 4);
        cpasync16(sbase + APLANE + sw, bh + go);
    }
    asm volatile("cp.async.commit_group;" ::: "memory");
}

template <int KTOT, int EPI>
__global__ void __launch_bounds__(64, 4) hgemm(
    const __half* __restrict__ A, long sA,
    const __half* __restrict__ Bh, long sB,
    const float* __restrict__ bias,
    __half* __restrict__ O,
    float* __restrict__ mp) {
    extern __shared__ __align__(1024) char smem[];
    uint32_t sb = s2u(smem);
    const int tid = threadIdx.x, lane = tid & 31, wid = tid >> 5;
    const int nT = blockIdx.x, mT = blockIdx.y, b = blockIdx.z;
    const int mBase = mT * 64, nBase = nT * 128;
    const int n0w = wid * 64;   // warp covers full 64 M rows, its own 64 N cols

    const __half* pA = A + (size_t)b * sA + (size_t)mBase * KTOT;
    const __half* pB = Bh + (size_t)b * sB + (size_t)nBase * KTOT;

    constexpr int NCH = KTOT / 64;
    issue_chunk(sb + 0 * STAGE, tid, pA, pB, KTOT);
    issue_chunk(sb + 1 * STAGE, tid, pA + 64, pB + 64, KTOT);

    float acc[4][8][4] = {};

    const uint32_t aoff0 = (uint32_t)(lane & 15) * 128;
    const int ax = lane & 7, kb = lane >> 4;
    const int grp = lane >> 3;
    const int brow0 = n0w + (lane & 7) + ((grp & 2) << 2);
    const uint32_t boff0 = (uint32_t)brow0 * 128;
    const int bx = brow0 & 7, kgb = grp & 1;

    for (int c = 0; c < NCH; c++) {
        if (c + 1 < NCH) asm volatile("cp.async.wait_group 1;" ::: "memory");
        else             asm volatile("cp.async.wait_group 0;" ::: "memory");
        __syncthreads();

        const uint32_t s0 = sb + (c & 1) * STAGE;
#pragma unroll
        for (int ks = 0; ks < 4; ks++) {
            uint32_t ah[4][4], bf[4][4];
            const uint32_t kxa = (uint32_t)((((ks << 1) | kb)) ^ ax) << 4;
#pragma unroll
            for (int mt = 0; mt < 4; mt++)
                ldsm4(s0 + aoff0 + mt * 2048 + kxa, ah[mt]);
            const uint32_t kxb = (uint32_t)((((ks << 1) | kgb)) ^ bx) << 4;
#pragma unroll
            for (int np = 0; np < 4; np++)
                ldsm4(s0 + APLANE + boff0 + np * 2048 + kxb, bf[np]);
#pragma unroll
            for (int np = 0; np < 4; np++)
#pragma unroll
                for (int mt = 0; mt < 4; mt++)
#pragma unroll
                    for (int j = 0; j < 2; j++)
                        mma16816(acc[mt][np * 2 + j], ah[mt], bf[np] + 2 * j);
        }
        __syncthreads();
        if (c + 2 < NCH)
            issue_chunk(sb + (c & 1) * STAGE, tid,
                        pA + (c + 2) * 64, pB + (c + 2) * 64, KTOT);
    }

    // accum -> padded fp32 smem (64 x 128, stride PADW)
    float* fsm = (float*)smem;
    {
        const int r0 = lane >> 2, c0 = (lane & 3) * 2;
#pragma unroll
        for (int mt = 0; mt < 4; mt++)
#pragma unroll
            for (int nt = 0; nt < 8; nt++) {
                int rr = mt * 16 + r0;
                int cc = n0w + nt * 8 + c0;
                fsm[rr * PADW + cc]           = acc[mt][nt][0];
                fsm[rr * PADW + cc + 1]       = acc[mt][nt][1];
                fsm[(rr + 8) * PADW + cc]     = acc[mt][nt][2];
                fsm[(rr + 8) * PADW + cc + 1] = acc[mt][nt][3];
            }
    }
    __syncthreads();

    if constexpr (EPI == 0) {
        // relu + fp16 row-major out; thread = 1 row of 128 cols
        const int row = tid;
        const float* src = fsm + row * PADW;
        size_t go = ((size_t)(b * N_ + mBase + row)) * H_ + nBase;
#pragma unroll
        for (int q = 0; q < 16; q++) {
            uint32_t hp[4];
#pragma unroll
            for (int j = 0; j < 4; j++) {
                float v0 = fmaxf(src[q * 8 + j * 2], 0.0f);
                float v1 = fmaxf(src[q * 8 + j * 2 + 1], 0.0f);
                hp[j] = pack2h(__float2half(v0), __float2half(v1));
            }
            *(uint4*)(O + go + q * 8) = make_uint4(hp[0], hp[1], hp[2], hp[3]);
        }
    } else if constexpr (EPI == 1) {
        // bias + fp16 transposed ([N,K]) out; thread handles 2 n-rows of 64 m
#pragma unroll
        for (int r = 0; r < 2; r++) {
            const int n = tid * 2 + r;
            const float bv = bias[nBase + n];
            size_t go = ((size_t)(b * H_ + nBase + n)) * N_ + mBase;
#pragma unroll
            for (int q = 0; q < 8; q++) {
                uint32_t hp[4];
#pragma unroll
                for (int j = 0; j < 4; j++) {
                    float v0 = fsm[(q * 8 + j * 2) * PADW + n] + bv;
                    float v1 = fsm[(q * 8 + j * 2 + 1) * PADW + n] + bv;
                    hp[j] = pack2h(__float2half(v0), __float2half(v1));
                }
                *(uint4*)(O + go + q * 8) = make_uint4(hp[0], hp[1], hp[2], hp[3]);
            }
        }
    } else {
        // relu + partial column sums (mean path); thread handles 2 cols
#pragma unroll
        for (int r = 0; r < 2; r++) {
            const int col = tid * 2 + r;
            float s = 0.0f;
#pragma unroll 16
            for (int rr = 0; rr < 64; rr++)
                s += fmaxf(fsm[rr * PADW + col], 0.0f);
            mp[((size_t)mT * B_ + b) * H_ + nBase + col] = s;
        }
    }
}

// ---------------------------------------------------------------------------
// Single-pass z reductions with MUFU sigmoid: ONE sigmoid per element.
// Row sums direct; column sums as per-strip partials (combined by dinv_kernel).
// grid (B_, 8 strips of 32 rows), block 256 (8 warps x 4 rows).
// ---------------------------------------------------------------------------
__global__ void zsums_kernel(const float* __restrict__ z) {
    int b = blockIdx.x, strip = blockIdx.y;
    int lane = threadIdx.x & 31, w = threadIdx.x >> 5;
    const float* Z = z + (size_t)b * N_ * N_ + (size_t)strip * 32 * N_;
    __shared__ float scol[8][N_];
    float colacc[8];
#pragma unroll
    for (int c = 0; c < 8; c++) colacc[c] = 0.0f;
#pragma unroll
    for (int rr = 0; rr < 4; rr++) {
        int row = w * 4 + rr;
        float rs = 0.0f;
#pragma unroll
        for (int c = 0; c < 8; c++) {
            float v = sigmoid_mufu(Z[(size_t)row * N_ + lane + 32 * c]);
            rs += v;
            colacc[c] += v;
        }
#pragma unroll
        for (int o = 16; o; o >>= 1) rs += __shfl_down_sync(0xffffffffu, rs, o);
        if (lane == 0) g_rowsum[b * N_ + strip * 32 + row] = rs;
    }
#pragma unroll
    for (int c = 0; c < 8; c++) scol[w][lane + 32 * c] = colacc[c];
    __syncthreads();
    int col = threadIdx.x;
    float s = scol[0][col];
#pragma unroll
    for (int k = 1; k < 8; k++) s += scol[k][col];
    g_colpart[((size_t)b * 8 + strip) * N_ + col] = s;
}

// Deterministic combine + dinv precompute. grid B_, 256 threads.
__global__ void dinv_kernel() {
    int b = blockIdx.x, col = threadIdx.x;
    const float* p = g_colpart + (size_t)b * 8 * N_;
    float s = p[col];
#pragma unroll
    for (int k = 1; k < 8; k++) s += p[k * N_ + col];
    float D = 1.0f + 0.5f * (g_rowsum[b * N_ + col] + s) + 1e-6f;
    g_dinv[b * N_ + col] = rsqrtf(D);
}

// ---------------------------------------------------------------------------
// Fused prep: blocks [0,128): XW1^T (2 nodes/block); [128,384): w2^T tile;
// [384,640): w3^T tile. 1024 threads. All outputs single fp16 (B-side).
// ---------------------------------------------------------------------------
__global__ void prep_kernel(const float* __restrict__ X, const float* __restrict__ w1,
                            const float* __restrict__ b1,
                            const float* __restrict__ w2, const float* __restrict__ w3) {
    int bx = blockIdx.x, tid = threadIdx.x;
    if (bx < 128) {
        int i = bx * 2 + (tid >> 9);   // node
        int h = tid & 511;
        __shared__ float xr[2][F_];
        if (h < F_) xr[tid >> 9][h] = X[i * F_ + h];
        __syncthreads();
        float acc = b1[h];
#pragma unroll 8
        for (int k = 0; k < F_; k++) acc = fmaf(xr[tid >> 9][k], w1[k * H_ + h], acc);
        g_XW1t[h * N_ + i] = __float2half(acc);
    } else {
        const float* w = (bx < 384) ? w2 : w3;
        __half* thi = (bx < 384) ? g_w2t : g_w3t;
        int t = (bx < 384) ? bx - 128 : bx - 384;
        int n0 = (t & 15) * 32, k0 = (t >> 4) * 32;
        int tx = tid & 31, ty = tid >> 5;
        __shared__ float tt[32][33];
        tt[ty][tx] = w[(k0 + ty) * H_ + n0 + tx];
        __syncthreads();
        thi[(n0 + ty) * H_ + k0 + tx] = __float2half(tt[tx][ty]);
    }
}

// ---------------------------------------------------------------------------
// normA symmetric tile-pair kernel, vectorized: 256 threads, 4 elems/thread,
// float4 z loads, smem-cached dinv, uint2 (4 x fp16) stores. z read once.
// grid (36 upper-tri block pairs, B_).
// ---------------------------------------------------------------------------
__global__ void __launch_bounds__(256) norma_kernel(const float* __restrict__ z) {
    int p = blockIdx.x, b = blockIdx.y;
    int bi = 0, rem = p;
    while (rem >= 8 - bi) { rem -= 8 - bi; bi++; }
    int bj = bi + rem;
    int i0 = bi * 32, j0 = bj * 32;
    const int tid = threadIdx.x;
    const int ty = tid >> 3;
    const int tx4 = (tid & 7) * 4;

    __shared__ float tA[32][33];
    __shared__ float tB[32][33];
    __shared__ float di[32], dj[32];

    const float* Z = z + (size_t)b * N_ * N_;
    const bool diag = (bi == bj);

    float4 va = *(const float4*)&Z[(size_t)(i0 + ty) * N_ + j0 + tx4];
    tA[ty][tx4 + 0] = sigmoid_fast(va.x);
    tA[ty][tx4 + 1] = sigmoid_fast(va.y);
    tA[ty][tx4 + 2] = sigmoid_fast(va.z);
    tA[ty][tx4 + 3] = sigmoid_fast(va.w);
    if (!diag) {
        float4 vb = *(const float4*)&Z[(size_t)(j0 + ty) * N_ + i0 + tx4];
        tB[ty][tx4 + 0] = sigmoid_fast(vb.x);
        tB[ty][tx4 + 1] = sigmoid_fast(vb.y);
        tB[ty][tx4 + 2] = sigmoid_fast(vb.z);
        tB[ty][tx4 + 3] = sigmoid_fast(vb.w);
    }
    if (tid < 32)              di[tid] = g_dinv[b * N_ + i0 + tid];
    else if (tid < 64)         dj[tid - 32] = g_dinv[b * N_ + j0 + tid - 32];
    __syncthreads();

    {
        const float dv = di[ty];
        __half h[4];
#pragma unroll
        for (int k = 0; k < 4; k++) {
            int j = tx4 + k;
            float at = diag ? tA[j][ty] : tB[j][ty];
            float v = 0.5f * (tA[ty][j] + at);
            if (diag && ty == j) v += 1.0f;
            h[k] = __float2half(v * dv * dj[j]);
        }
        uint2 pk = make_uint2(pack2h(h[0], h[1]), pack2h(h[2], h[3]));
        *(uint2*)&g_nA[(size_t)b * N_ * N_ + (size_t)(i0 + ty) * N_ + j0 + tx4] = pk;
    }
    if (!diag) {
        const float dv = dj[ty];
        __half h[4];
#pragma unroll
        for (int k = 0; k < 4; k++) {
            int j = tx4 + k;
            float v = 0.5f * (tB[ty][j] + tA[j][ty]);
            h[k] = __float2half(v * dv * di[j]);
        }
        uint2 pk = make_uint2(pack2h(h[0], h[1]), pack2h(h[2], h[3]));
        *(uint2*)&g_nA[(size_t)b * N_ * N_ + (size_t)(j0 + ty) * N_ + i0 + tx4] = pk;
    }
}

// ---------------------------------------------------------------------------
// logits from meanpart (4 mT partials)
// ---------------------------------------------------------------------------
__global__ void readout_kernel(const float* __restrict__ fcw, const float* __restrict__ fcb,
                               float* __restrict__ out) {
    int b = blockIdx.x;
    int h = threadIdx.x;
    float ge = (g_meanpart[b * H_ + h] +
                g_meanpart[(size_t)B_ * H_ + b * H_ + h] +
                g_meanpart[2 * (size_t)B_ * H_ + b * H_ + h] +
                g_meanpart[3 * (size_t)B_ * H_ + b * H_ + h]) * (1.0f / N_);
    __shared__ float s0[H_], s1[H_];
    s0[h] = ge * fcw[h * 2 + 0];
    s1[h] = ge * fcw[h * 2 + 1];
    __syncthreads();
    for (int st = 256; st > 0; st >>= 1) {
        if (h < st) { s0[h] += s0[h + st]; s1[h] += s1[h + st]; }
        __syncthreads();
    }
    if (h == 0) {
        out[b * 2 + 0] = s0[0] + fcb[0];
        out[b * 2 + 1] = s1[0] + fcb[1];
    }
}

// ---------------------------------------------------------------------------
extern "C" void kernel_launch(void* const* d_in, const int* in_sizes, int n_in,
                              void* d_out, int out_size) {
    const float* z   = (const float*)d_in[0];
    const float* ne  = (const float*)d_in[1];
    const float* w1  = (const float*)d_in[2];
    const float* b1  = (const float*)d_in[3];
    const float* w2  = (const float*)d_in[4];
    const float* b2  = (const float*)d_in[5];
    const float* w3  = (const float*)d_in[6];
    const float* b3  = (const float*)d_in[7];
    const float* fcw = (const float*)d_in[8];
    const float* fcb = (const float*)d_in[9];
    float* out = (float*)d_out;

    __half *pnA, *pH, *pYt, *pXW1t, *pw2t, *pw3t;
    float* pmean;
    cudaGetSymbolAddress((void**)&pnA, g_nA);
    cudaGetSymbolAddress((void**)&pH, g_H);
    cudaGetSymbolAddress((void**)&pYt, g_Yt);
    cudaGetSymbolAddress((void**)&pXW1t, g_XW1t);
    cudaGetSymbolAddress((void**)&pw2t, g_w2t);
    cudaGetSymbolAddress((void**)&pw3t, g_w3t);
    cudaGetSymbolAddress((void**)&pmean, g_meanpart);

    cudaFuncSetAttribute(hgemm<256, 0>, cudaFuncAttributeMaxDynamicSharedMemorySize, SMEM_G);
    cudaFuncSetAttribute(hgemm<512, 1>, cudaFuncAttributeMaxDynamicSharedMemorySize, SMEM_G);
    cudaFuncSetAttribute(hgemm<256, 2>, cudaFuncAttributeMaxDynamicSharedMemorySize, SMEM_G);

    zsums_kernel<<<dim3(B_, 8), 256>>>(z);
    dinv_kernel<<<B_, 256>>>();
    prep_kernel<<<640, 1024>>>(ne, w1, b1, w2, w3);
    norma_kernel<<<dim3(36, B_), 256>>>(z);

    dim3 gg(4, 4, B_);   // nT (128-wide), mT (64-tall), batch
    // H1 = relu(normA @ XW1)
    hgemm<256, 0><<<gg, 64, SMEM_G>>>(pnA, (long)N_ * N_, pXW1t, 0, nullptr, pH, nullptr);
    // Y2^T = (H1 @ w2 + b2)^T
    hgemm<512, 1><<<gg, 64, SMEM_G>>>(pH, (long)N_ * H_, pw2t, 0, b2, pYt, nullptr);
    // H2 = relu(normA @ Y2)
    hgemm<256, 0><<<gg, 64, SMEM_G>>>(pnA, (long)N_ * N_, pYt, (long)H_ * N_, nullptr, pH, nullptr);
    // Y3^T = (H2 @ w3 + b3)^T
    hgemm<512, 1><<<gg, 64, SMEM_G>>>(pH, (long)N_ * H_, pw3t, 0, b3, pYt, nullptr);
    // meanpart = colsum(relu(normA @ Y3)) per m-tile
    hgemm<256, 2><<<gg, 64, SMEM_G>>>(pnA, (long)N_ * N_, pYt, (long)H_ * N_, nullptr, nullptr, pmean);

    readout_kernel<<<B_, H_>>>(fcw, fcb, out);
}